// round 7
// baseline (speedup 1.0000x reference)
#include <cuda_runtime.h>

#define NBATCH 8
#define NN 2048
#define FIN 128
#define ODIM 256
#define NROWS (NBATCH*NN)   // 16384

// Scratch (device globals — allocation is forbidden)
__device__ __align__(16) float g_XS[(size_t)NROWS * ODIM]; // X @ W^T (16 MB)
__device__ __align__(16) float g_P[(size_t)NROWS * 12];    // per j: dst[4], F1[4], F2[4]
__device__ __align__(16) float g_Q[(size_t)NROWS * 12];    // per i: thr[4] (=-src), E1[4], E2[4]

// ---------------------------------------------------------------------------
// Kernel 1: g_XS[m][n] = sum_k X[m][k] * W[n][k].  M-tile 128, N-tile 64, K = 128.
__global__ void __launch_bounds__(256, 2) gemm_kernel(const float* __restrict__ X,
                                                      const float* __restrict__ Wt) {
    extern __shared__ float sm[];
    float* Xs = sm;                 // [128 k][128 m] swizzled
    float* Ws = sm + 128 * 128;     // [128 k][64 n]  swizzled
    const int tid = threadIdx.x;
    const int w = tid >> 5, l = tid & 31;
    const int m0 = blockIdx.y * 128;
    const int n0 = blockIdx.x * 64;
    const int sw = l & 7;

    #pragma unroll
    for (int rr = 0; rr < 16; rr++) {
        int m = w * 16 + rr;
        float4 v = *(const float4*)(X + (size_t)(m0 + m) * FIN + 4 * l);
        int base = (4 * l) * 128 + (((m >> 2) ^ sw) << 2) + (m & 3);
        Xs[base] = v.x; Xs[base + 128] = v.y; Xs[base + 256] = v.z; Xs[base + 384] = v.w;
    }
    #pragma unroll
    for (int rr = 0; rr < 8; rr++) {
        int n = w * 8 + rr;
        float4 v = *(const float4*)(Wt + (size_t)(n0 + n) * FIN + 4 * l);
        int base = (4 * l) * 64 + (((n >> 2) ^ sw) << 2) + (n & 3);
        Ws[base] = v.x; Ws[base + 64] = v.y; Ws[base + 128] = v.z; Ws[base + 192] = v.w;
    }
    __syncthreads();

    const int tm = tid >> 4;
    const int tn = tid & 15;
    float acc[8][4];
    #pragma unroll
    for (int r = 0; r < 8; r++)
        #pragma unroll
        for (int c = 0; c < 4; c++) acc[r][c] = 0.0f;

    #pragma unroll 4
    for (int k = 0; k < 128; k++) {
        int s = (k >> 2) & 7;
        float4 a0 = *(const float4*)(Xs + k * 128 + ((tm ^ s) << 2));
        float4 a1 = *(const float4*)(Xs + k * 128 + (((16 + tm) ^ s) << 2));
        float4 bb = *(const float4*)(Ws + k * 64 + ((tn ^ s) << 2));
        float av[8] = {a0.x, a0.y, a0.z, a0.w, a1.x, a1.y, a1.z, a1.w};
        float bv[4] = {bb.x, bb.y, bb.z, bb.w};
        #pragma unroll
        for (int r = 0; r < 8; r++)
            #pragma unroll
            for (int c = 0; c < 4; c++)
                acc[r][c] += av[r] * bv[c];
    }

    #pragma unroll
    for (int r = 0; r < 8; r++) {
        int m = m0 + ((r < 4) ? (4 * tm + r) : (64 + 4 * tm + (r - 4)));
        *(float4*)(g_XS + (size_t)m * ODIM + n0 + 4 * tn) =
            make_float4(acc[r][0], acc[r][1], acc[r][2], acc[r][3]);
    }
}

// ---------------------------------------------------------------------------
// Kernel 2: per-row attention dots + exp tables. One warp per row.
__global__ void __launch_bounds__(256) prep_kernel(const float* __restrict__ a_src,
                                                   const float* __restrict__ a_dst) {
    int row = blockIdx.x * 8 + (threadIdx.x >> 5);
    int l = threadIdx.x & 31;
    const float* xr = g_XS + (size_t)row * ODIM;
    int c0 = l * 8;
    float4 x0 = *(const float4*)(xr + c0);
    float4 x1 = *(const float4*)(xr + c0 + 4);
    float4 s0 = *(const float4*)(a_src + c0);
    float4 s1 = *(const float4*)(a_src + c0 + 4);
    float4 d0 = *(const float4*)(a_dst + c0);
    float4 d1 = *(const float4*)(a_dst + c0 + 4);
    float ss = x0.x*s0.x + x0.y*s0.y + x0.z*s0.z + x0.w*s0.w
             + x1.x*s1.x + x1.y*s1.y + x1.z*s1.z + x1.w*s1.w;
    float dd = x0.x*d0.x + x0.y*d0.y + x0.z*d0.z + x0.w*d0.w
             + x1.x*d1.x + x1.y*d1.y + x1.z*d1.z + x1.w*d1.w;
    #pragma unroll
    for (int t = 1; t < 8; t <<= 1) {
        ss += __shfl_xor_sync(0xffffffffu, ss, t);
        dd += __shfl_xor_sync(0xffffffffu, dd, t);
    }
    if ((l & 7) == 0) {
        int h = l >> 3;
        float* Q = g_Q + (size_t)row * 12;
        float* P = g_P + (size_t)row * 12;
        Q[h]     = -ss;                 // threshold: dst_j >= -src_i  <=>  src+dst >= 0
        Q[4 + h] = __expf(ss);          // E1
        Q[8 + h] = __expf(0.2f * ss);   // E2
        P[h]     = dd;
        P[4 + h] = __expf(dd);          // F1
        P[8 + h] = __expf(0.2f * dd);   // F2
    }
}

// ---------------------------------------------------------------------------
// Kernel 3: masked softmax diagonal + output scaling.
// RW=2 to keep live registers ~60-70 (well under the 128 cap at occ 2) — no spills.
#define RW 2
__global__ void __launch_bounds__(256, 2) attn_kernel(const float* __restrict__ A,
                                                      float* __restrict__ out) {
    extern __shared__ float Ps[];   // [2048][12] = 96 KB
    const int b = blockIdx.y;
    const int i0 = blockIdx.x * 16;     // 16 rows per block (8 warps x 2 rows)
    const int tid = threadIdx.x;

    {   // stage per-j table for this batch: 6144 float4
        const float4* s4 = (const float4*)(g_P + (size_t)b * NN * 12);
        float4* d4 = (float4*)Ps;
        #pragma unroll
        for (int q = 0; q < 24; q++) d4[tid + q * 256] = s4[tid + q * 256];
    }
    __syncthreads();

    const int w = tid >> 5, l = tid & 31;
    const int ib = i0 + w * RW;

    float4 thrv[RW];
    const unsigned int* Arow[RW];
    #pragma unroll
    for (int r = 0; r < RW; r++) {
        thrv[r] = *(const float4*)(g_Q + ((size_t)b * NN + ib + r) * 12);
        Arow[r] = (const unsigned int*)(A + ((size_t)b * NN + ib + r) * (size_t)NN);
    }

    float4 accA[RW], accB[RW];
    #pragma unroll
    for (int r = 0; r < RW; r++) {
        accA[r] = make_float4(0.f, 0.f, 0.f, 0.f);
        accB[r] = make_float4(0.f, 0.f, 0.f, 0.f);
    }

    unsigned int a_pre[RW];
    #pragma unroll
    for (int r = 0; r < RW; r++) a_pre[r] = __ldg(Arow[r] + l);

    for (int j = l; j < NN; j += 32) {
        unsigned int a_cur[RW];
        #pragma unroll
        for (int r = 0; r < RW; r++) a_cur[r] = a_pre[r];
        int jn = (j + 32) & (NN - 1);       // branch-free prefetch wrap
        #pragma unroll
        for (int r = 0; r < RW; r++) a_pre[r] = __ldg(Arow[r] + jn);

        const float* p = Ps + j * 12;
        float4 dd = *(const float4*)p;
        float4 f1 = *(const float4*)(p + 4);
        float4 f2 = *(const float4*)(p + 8);
        const int i1x = __float_as_int(f1.x), i1y = __float_as_int(f1.y),
                  i1z = __float_as_int(f1.z), i1w = __float_as_int(f1.w);
        const int i2x = __float_as_int(f2.x), i2y = __float_as_int(f2.y),
                  i2z = __float_as_int(f2.z), i2w = __float_as_int(f2.w);
        #pragma unroll
        for (int r = 0; r < RW; r++) {
            const float a = __uint_as_float(a_cur[r]);   // exactly 0.0f or 1.0f
            const int sx = __float_as_int(dd.x - thrv[r].x) >> 31;  // all-ones iff cond false
            const int sy = __float_as_int(dd.y - thrv[r].y) >> 31;
            const int sz = __float_as_int(dd.z - thrv[r].z) >> 31;
            const int sw2 = __float_as_int(dd.w - thrv[r].w) >> 31;
            accA[r].x = fmaf(a, __int_as_float(i1x & ~sx),  accA[r].x);
            accB[r].x = fmaf(a, __int_as_float(i2x &  sx),  accB[r].x);
            accA[r].y = fmaf(a, __int_as_float(i1y & ~sy),  accA[r].y);
            accB[r].y = fmaf(a, __int_as_float(i2y &  sy),  accB[r].y);
            accA[r].z = fmaf(a, __int_as_float(i1z & ~sz),  accA[r].z);
            accB[r].z = fmaf(a, __int_as_float(i2z &  sz),  accB[r].z);
            accA[r].w = fmaf(a, __int_as_float(i1w & ~sw2), accA[r].w);
            accB[r].w = fmaf(a, __int_as_float(i2w &  sw2), accB[r].w);
        }
    }

    #pragma unroll
    for (int r = 0; r < RW; r++) {
        int n = ib + r;
        float sA[4] = {accA[r].x, accA[r].y, accA[r].z, accA[r].w};
        float sB[4] = {accB[r].x, accB[r].y, accB[r].z, accB[r].w};
        #pragma unroll
        for (int h = 0; h < 4; h++) {
            #pragma unroll
            for (int d = 16; d; d >>= 1) {
                sA[h] += __shfl_xor_sync(0xffffffffu, sA[h], d);
                sB[h] += __shfl_xor_sync(0xffffffffu, sB[h], d);
            }
        }
        const float* q = g_Q + ((size_t)b * NN + n) * 12;
        const float* pi = Ps + n * 12;
        float wgt[4];
        #pragma unroll
        for (int h = 0; h < 4; h++) {
            float thr = q[h], e1 = q[4 + h], e2 = q[8 + h];
            float ddi = pi[h], f1i = pi[4 + h], f2i = pi[8 + h];
            float num = (ddi >= thr) ? (e1 * f1i) : (e2 * f2i);
            float den = e1 * sA[h] + e2 * sB[h];
            wgt[h] = num / den;
        }
        int c0 = l * 8;
        float wh = wgt[l >> 3];
        const float* xr = g_XS + (size_t)((size_t)b * NN + n) * ODIM + c0;
        float4 x0 = *(const float4*)xr;
        float4 x1 = *(const float4*)(xr + 4);
        float* o = out + (size_t)((size_t)b * NN + n) * ODIM + c0;
        *(float4*)o       = make_float4(wh * x0.x, wh * x0.y, wh * x0.z, wh * x0.w);
        *(float4*)(o + 4) = make_float4(wh * x1.x, wh * x1.y, wh * x1.z, wh * x1.w);
    }
}

// ---------------------------------------------------------------------------
extern "C" void kernel_launch(void* const* d_in, const int* in_sizes, int n_in,
                              void* d_out, int out_size) {
    const float* A     = (const float*)d_in[0];
    const float* X     = (const float*)d_in[1];
    const float* W     = (const float*)d_in[2];
    const float* a_src = (const float*)d_in[3];
    const float* a_dst = (const float*)d_in[4];
    float* out = (float*)d_out;

    cudaFuncSetAttribute(gemm_kernel, cudaFuncAttributeMaxDynamicSharedMemorySize, 96 * 1024);
    cudaFuncSetAttribute(attn_kernel, cudaFuncAttributeMaxDynamicSharedMemorySize, 96 * 1024);

    dim3 ggrid(ODIM / 64, NROWS / 128);
    gemm_kernel<<<ggrid, 256, 96 * 1024>>>(X, W);
    prep_kernel<<<NROWS / 8, 256>>>(a_src, a_dst);
    dim3 agrid(NN / 16, NBATCH);
    attn_kernel<<<agrid, 256, 96 * 1024>>>(A, out);
}

// round 8
// speedup vs baseline: 2.0953x; 2.0953x over previous
#include <cuda_runtime.h>

#define NBATCH 8
#define NN 2048
#define FIN 128
#define ODIM 256
#define NROWS (NBATCH*NN)   // 16384

// Scratch (device globals — allocation is forbidden)
__device__ __align__(16) float g_XS[(size_t)NROWS * ODIM]; // X @ W^T (16 MB)
__device__ __align__(16) float g_P[(size_t)NBATCH * 12 * NN]; // SoA per batch: [12][2048]
__device__ __align__(16) float g_Q[(size_t)NROWS * 12];    // per i: thr[4] (=-src), E1[4], E2[4]

// ---------------------------------------------------------------------------
// Kernel 1: g_XS[m][n] = sum_k X[m][k] * W[n][k].  M-tile 128, N-tile 64, K = 128.
__global__ void __launch_bounds__(256, 2) gemm_kernel(const float* __restrict__ X,
                                                      const float* __restrict__ Wt) {
    extern __shared__ float sm[];
    float* Xs = sm;                 // [128 k][128 m] swizzled
    float* Ws = sm + 128 * 128;     // [128 k][64 n]  swizzled
    const int tid = threadIdx.x;
    const int w = tid >> 5, l = tid & 31;
    const int m0 = blockIdx.y * 128;
    const int n0 = blockIdx.x * 64;
    const int sw = l & 7;

    #pragma unroll
    for (int rr = 0; rr < 16; rr++) {
        int m = w * 16 + rr;
        float4 v = *(const float4*)(X + (size_t)(m0 + m) * FIN + 4 * l);
        int base = (4 * l) * 128 + (((m >> 2) ^ sw) << 2) + (m & 3);
        Xs[base] = v.x; Xs[base + 128] = v.y; Xs[base + 256] = v.z; Xs[base + 384] = v.w;
    }
    #pragma unroll
    for (int rr = 0; rr < 8; rr++) {
        int n = w * 8 + rr;
        float4 v = *(const float4*)(Wt + (size_t)(n0 + n) * FIN + 4 * l);
        int base = (4 * l) * 64 + (((n >> 2) ^ sw) << 2) + (n & 3);
        Ws[base] = v.x; Ws[base + 64] = v.y; Ws[base + 128] = v.z; Ws[base + 192] = v.w;
    }
    __syncthreads();

    const int tm = tid >> 4;
    const int tn = tid & 15;
    float acc[8][4];
    #pragma unroll
    for (int r = 0; r < 8; r++)
        #pragma unroll
        for (int c = 0; c < 4; c++) acc[r][c] = 0.0f;

    #pragma unroll 4
    for (int k = 0; k < 128; k++) {
        int s = (k >> 2) & 7;
        float4 a0 = *(const float4*)(Xs + k * 128 + ((tm ^ s) << 2));
        float4 a1 = *(const float4*)(Xs + k * 128 + (((16 + tm) ^ s) << 2));
        float4 bb = *(const float4*)(Ws + k * 64 + ((tn ^ s) << 2));
        float av[8] = {a0.x, a0.y, a0.z, a0.w, a1.x, a1.y, a1.z, a1.w};
        float bv[4] = {bb.x, bb.y, bb.z, bb.w};
        #pragma unroll
        for (int r = 0; r < 8; r++)
            #pragma unroll
            for (int c = 0; c < 4; c++)
                acc[r][c] += av[r] * bv[c];
    }

    #pragma unroll
    for (int r = 0; r < 8; r++) {
        int m = m0 + ((r < 4) ? (4 * tm + r) : (64 + 4 * tm + (r - 4)));
        *(float4*)(g_XS + (size_t)m * ODIM + n0 + 4 * tn) =
            make_float4(acc[r][0], acc[r][1], acc[r][2], acc[r][3]);
    }
}

// ---------------------------------------------------------------------------
// Kernel 2: per-row attention dots + exp tables. One warp per row.
// g_P written SoA per batch: plane c, element j  ->  g_P[(b*12 + c)*NN + j]
__global__ void __launch_bounds__(256) prep_kernel(const float* __restrict__ a_src,
                                                   const float* __restrict__ a_dst) {
    int row = blockIdx.x * 8 + (threadIdx.x >> 5);
    int l = threadIdx.x & 31;
    const float* xr = g_XS + (size_t)row * ODIM;
    int c0 = l * 8;
    float4 x0 = *(const float4*)(xr + c0);
    float4 x1 = *(const float4*)(xr + c0 + 4);
    float4 s0 = *(const float4*)(a_src + c0);
    float4 s1 = *(const float4*)(a_src + c0 + 4);
    float4 d0 = *(const float4*)(a_dst + c0);
    float4 d1 = *(const float4*)(a_dst + c0 + 4);
    float ss = x0.x*s0.x + x0.y*s0.y + x0.z*s0.z + x0.w*s0.w
             + x1.x*s1.x + x1.y*s1.y + x1.z*s1.z + x1.w*s1.w;
    float dd = x0.x*d0.x + x0.y*d0.y + x0.z*d0.z + x0.w*d0.w
             + x1.x*d1.x + x1.y*d1.y + x1.z*d1.z + x1.w*d1.w;
    #pragma unroll
    for (int t = 1; t < 8; t <<= 1) {
        ss += __shfl_xor_sync(0xffffffffu, ss, t);
        dd += __shfl_xor_sync(0xffffffffu, dd, t);
    }
    if ((l & 7) == 0) {
        int h = l >> 3;
        int b = row >> 11, j = row & (NN - 1);
        float* Q = g_Q + (size_t)row * 12;
        float* P = g_P + (size_t)b * 12 * NN;
        Q[h]     = -ss;                 // threshold: dst_j >= -src_i  <=>  src+dst >= 0
        Q[4 + h] = __expf(ss);          // E1
        Q[8 + h] = __expf(0.2f * ss);   // E2
        P[h * NN + j]       = dd;
        P[(4 + h) * NN + j] = __expf(dd);          // F1
        P[(8 + h) * NN + j] = __expf(0.2f * dd);   // F2
    }
}

// ---------------------------------------------------------------------------
// Kernel 3: masked softmax diagonal + output scaling.
// Vectorized A: lane l owns j = 4l..4l+3 per 128-wide block; 16 iterations total.
// Tables in smem SoA [12][2048] -> stride-4-word LDS.128, conflict-free.
#define RW 4
__global__ void __launch_bounds__(256, 2) attn_kernel(const float* __restrict__ A,
                                                      float* __restrict__ out) {
    extern __shared__ float S[];   // [12][2048] = 96 KB
    const int b = blockIdx.y;
    const int i0 = blockIdx.x * 32;
    const int tid = threadIdx.x;

    {   // stage per-batch SoA table: 6144 float4 (straight copy)
        const float4* s4 = (const float4*)(g_P + (size_t)b * 12 * NN);
        float4* d4 = (float4*)S;
        #pragma unroll
        for (int q = 0; q < 24; q++) d4[tid + q * 256] = s4[tid + q * 256];
    }
    __syncthreads();

    const int w = tid >> 5, l = tid & 31;
    const int ib = i0 + w * RW;

    float thr[RW][4];
    const float4* Arow[RW];
    #pragma unroll
    for (int r = 0; r < RW; r++) {
        const float* q = g_Q + ((size_t)b * NN + ib + r) * 12;
        #pragma unroll
        for (int h = 0; h < 4; h++) thr[r][h] = q[h];
        Arow[r] = (const float4*)(A + ((size_t)b * NN + ib + r) * (size_t)NN);
    }

    float accA[RW][4], accB[RW][4];
    #pragma unroll
    for (int r = 0; r < RW; r++)
        #pragma unroll
        for (int h = 0; h < 4; h++) { accA[r][h] = 0.f; accB[r][h] = 0.f; }

    float4 a_nxt[RW];
    #pragma unroll
    for (int r = 0; r < RW; r++) a_nxt[r] = __ldg(Arow[r] + l);

    #pragma unroll 1
    for (int it = 0; it < 16; it++) {
        float4 a_cur[RW];
        #pragma unroll
        for (int r = 0; r < RW; r++) a_cur[r] = a_nxt[r];
        int itn = (it + 1) & 15;                       // branch-free wrap
        #pragma unroll
        for (int r = 0; r < RW; r++) a_nxt[r] = __ldg(Arow[r] + itn * 32 + l);

        const int jl = it * 128 + 4 * l;               // this lane's base j
        #pragma unroll
        for (int h = 0; h < 4; h++) {
            float4 dd = *(const float4*)(S + h * NN + jl);
            float4 f1 = *(const float4*)(S + (4 + h) * NN + jl);
            float4 f2 = *(const float4*)(S + (8 + h) * NN + jl);
            #pragma unroll
            for (int r = 0; r < RW; r++) {
                const float t = thr[r][h];
                accA[r][h] = fmaf(a_cur[r].x, (dd.x >= t) ? f1.x : 0.0f, accA[r][h]);
                accB[r][h] = fmaf(a_cur[r].x, (dd.x >= t) ? 0.0f : f2.x, accB[r][h]);
                accA[r][h] = fmaf(a_cur[r].y, (dd.y >= t) ? f1.y : 0.0f, accA[r][h]);
                accB[r][h] = fmaf(a_cur[r].y, (dd.y >= t) ? 0.0f : f2.y, accB[r][h]);
                accA[r][h] = fmaf(a_cur[r].z, (dd.z >= t) ? f1.z : 0.0f, accA[r][h]);
                accB[r][h] = fmaf(a_cur[r].z, (dd.z >= t) ? 0.0f : f2.z, accB[r][h]);
                accA[r][h] = fmaf(a_cur[r].w, (dd.w >= t) ? f1.w : 0.0f, accA[r][h]);
                accB[r][h] = fmaf(a_cur[r].w, (dd.w >= t) ? 0.0f : f2.w, accB[r][h]);
            }
        }
    }

    #pragma unroll
    for (int r = 0; r < RW; r++) {
        int n = ib + r;
        float sA[4], sB[4];
        #pragma unroll
        for (int h = 0; h < 4; h++) { sA[h] = accA[r][h]; sB[h] = accB[r][h]; }
        #pragma unroll
        for (int h = 0; h < 4; h++) {
            #pragma unroll
            for (int d = 16; d; d >>= 1) {
                sA[h] += __shfl_xor_sync(0xffffffffu, sA[h], d);
                sB[h] += __shfl_xor_sync(0xffffffffu, sB[h], d);
            }
        }
        const float* q = g_Q + ((size_t)b * NN + n) * 12;
        float wgt[4];
        #pragma unroll
        for (int h = 0; h < 4; h++) {
            float t = q[h], e1 = q[4 + h], e2 = q[8 + h];
            float ddi = S[h * NN + n];
            float f1i = S[(4 + h) * NN + n];
            float f2i = S[(8 + h) * NN + n];
            float num = (ddi >= t) ? (e1 * f1i) : (e2 * f2i);
            float den = e1 * sA[h] + e2 * sB[h];
            wgt[h] = num / den;
        }
        int c0 = l * 8;
        float wh = wgt[l >> 3];
        const float* xr = g_XS + (size_t)((size_t)b * NN + n) * ODIM + c0;
        float4 x0 = *(const float4*)xr;
        float4 x1 = *(const float4*)(xr + 4);
        float* o = out + (size_t)((size_t)b * NN + n) * ODIM + c0;
        *(float4*)o       = make_float4(wh * x0.x, wh * x0.y, wh * x0.z, wh * x0.w);
        *(float4*)(o + 4) = make_float4(wh * x1.x, wh * x1.y, wh * x1.z, wh * x1.w);
    }
}

// ---------------------------------------------------------------------------
extern "C" void kernel_launch(void* const* d_in, const int* in_sizes, int n_in,
                              void* d_out, int out_size) {
    const float* A     = (const float*)d_in[0];
    const float* X     = (const float*)d_in[1];
    const float* W     = (const float*)d_in[2];
    const float* a_src = (const float*)d_in[3];
    const float* a_dst = (const float*)d_in[4];
    float* out = (float*)d_out;

    cudaFuncSetAttribute(gemm_kernel, cudaFuncAttributeMaxDynamicSharedMemorySize, 96 * 1024);
    cudaFuncSetAttribute(attn_kernel, cudaFuncAttributeMaxDynamicSharedMemorySize, 96 * 1024);

    dim3 ggrid(ODIM / 64, NROWS / 128);
    gemm_kernel<<<ggrid, 256, 96 * 1024>>>(X, W);
    prep_kernel<<<NROWS / 8, 256>>>(a_src, a_dst);
    dim3 agrid(NN / 32, NBATCH);
    attn_kernel<<<agrid, 256, 96 * 1024>>>(A, out);
}